// round 6
// baseline (speedup 1.0000x reference)
#include <cuda_runtime.h>
#include <math.h>

#define BB 8
#define CC 4
#define HH 192
#define WW 192
#define HW (HH*WW)
#define NP 24          // (batch, class) pairs: 8 * 3
#define NM 48          // masks: pair*2 + {0:pred surface, 1:gt surface}
#define SENT_KEY 73727 // sentinel key for f == 1e9 (empty source surface)

__device__ unsigned char  d_pred[BB*HW];
__device__ unsigned char  d_surf[NM*HW];
__device__ unsigned char  d_cols[NM*HW];     // per-row compacted sample columns
__device__ short          d_cnt[NM*HH];      // samples per row
__device__ unsigned short d_g16[NM*HW];      // column-pass squared distance (65535 = inf)
__device__ int            d_keys[NM*HW];     // appended squared-distance keys per mask
__device__ int            d_kcnt[NM];        // append counters
__device__ float          d_res[NM*2];       // [m][0]=p95, [m][1]=p100

// ---------------------------------------------------------------- argmax (softmax monotone; first-max tie rule)
// Also clears the per-mask key counters (runs before rowpass).
__global__ void argmax_kernel(const float* __restrict__ logits) {
    int idx = blockIdx.x*blockDim.x + threadIdx.x;
    if (idx < NM) d_kcnt[idx] = 0;
    int pix4 = idx * 4;
    if (pix4 >= BB*HW) return;
    int b = pix4 / HW;
    int p = pix4 - b*HW;
    const float* base = logits + (size_t)b*CC*HW + p;
    float4 v0 = *(const float4*)(base);
    float4 v1 = *(const float4*)(base + HW);
    float4 v2 = *(const float4*)(base + 2*HW);
    float4 v3 = *(const float4*)(base + 3*HW);
    uchar4 r;
    #define AMAX(comp, dst) { \
        float bv = v0.comp; int bi = 0; \
        if (v1.comp > bv) { bv = v1.comp; bi = 1; } \
        if (v2.comp > bv) { bv = v2.comp; bi = 2; } \
        if (v3.comp > bv) { bv = v3.comp; bi = 3; } \
        dst = (unsigned char)bi; }
    AMAX(x, r.x) AMAX(y, r.y) AMAX(z, r.z) AMAX(w, r.w)
    #undef AMAX
    *(uchar4*)(d_pred + pix4) = r;
}

// ---------------------------------------------------------------- fused surface + row compaction
// One warp per (pair,row). Computes pred & gt 4-neighbor surfaces (border = background),
// writes d_surf (for colpass) and ballot-compacts surface columns into d_cols/d_cnt.
// target is int32 (JAX x64-disabled downcasts the reference's int64).
__global__ void surfcompact_kernel(const int* __restrict__ target) {
    int wid  = threadIdx.x >> 5;
    int lane = threadIdx.x & 31;
    int gw = blockIdx.x*4 + wid;                 // row id in [0, NP*HH)
    if (gw >= NP*HH) return;
    int pair = gw / HH;
    int i    = gw - pair*HH;
    int b = pair / 3;
    int c = pair - b*3 + 1;
    const unsigned char* P = d_pred + b*HW;
    const int* T = target + (size_t)b*HW;
    int mp = pair*2, mg = pair*2 + 1;
    unsigned char* outp = d_cols + mp*HW + i*WW;
    unsigned char* outg = d_cols + mg*HW + i*WW;
    int basep = 0, baseg = 0;
    #pragma unroll
    for (int ch = 0; ch < 6; ch++) {
        int j = ch*32 + lane;
        int pix = i*WW + j;
        // pred surface
        {
            bool fg = (P[pix] == c);
            bool s = false;
            if (fg) {
                bool up = (i > 0)    && (P[pix-WW] == c);
                bool dn = (i < HH-1) && (P[pix+WW] == c);
                bool lf = (j > 0)    && (P[pix-1]  == c);
                bool rt = (j < WW-1) && (P[pix+1]  == c);
                s = !(up && dn && lf && rt);
            }
            d_surf[mp*HW + pix] = s ? 1 : 0;
            unsigned msk = __ballot_sync(0xffffffffu, s);
            if (s) outp[basep + __popc(msk & ((1u << lane) - 1u))] = (unsigned char)j;
            basep += __popc(msk);
        }
        // gt surface
        {
            bool fg = (T[pix] == c);
            bool s = false;
            if (fg) {
                bool up = (i > 0)    && (T[pix-WW] == c);
                bool dn = (i < HH-1) && (T[pix+WW] == c);
                bool lf = (j > 0)    && (T[pix-1]  == c);
                bool rt = (j < WW-1) && (T[pix+1]  == c);
                s = !(up && dn && lf && rt);
            }
            d_surf[mg*HW + pix] = s ? 1 : 0;
            unsigned msk = __ballot_sync(0xffffffffu, s);
            if (s) outg[baseg + __popc(msk & ((1u << lane) - 1u))] = (unsigned char)j;
            baseg += __popc(msk);
        }
    }
    if (lane == 0) {
        d_cnt[mp*HH + i] = (short)basep;
        d_cnt[mg*HH + i] = (short)baseg;
    }
}

// ---------------------------------------------------------------- pass 1: per-column squared distance to nearest surface row
// grid (48 masks, 3 col-groups of 64). Forward: downward count into smem (0 <=> surface voxel).
// Backward: pure smem/register, write d^2 as u16 (65535 = empty column).
__global__ void colpass_kernel() {
    int m = blockIdx.x;
    int j = blockIdx.y*64 + threadIdx.x;
    int t = threadIdx.x;
    __shared__ unsigned char dtmp[HH*64];
    const unsigned char* s = d_surf + m*HW;
    unsigned short* g = d_g16 + m*HW;
    int cnt = 255;
    #pragma unroll 16
    for (int i = 0; i < HH; i++) {
        unsigned char sv = s[i*WW + j];
        cnt = sv ? 0 : min(cnt + 1, 255);
        dtmp[i*64 + t] = (unsigned char)cnt;
    }
    cnt = 255;
    #pragma unroll 16
    for (int i = HH-1; i >= 0; i--) {
        int du = (int)dtmp[i*64 + t];
        cnt = (du == 0) ? 0 : min(cnt + 1, 255);
        int d = min(cnt, du);
        g[i*WW + j] = (d >= HH) ? (unsigned short)65535 : (unsigned short)(d*d);
    }
}

// ---------------------------------------------------------------- pass 2: min-plus at sampled voxels, append keys
// f(i,j) = min_jp fma((j-jp),(j-jp), g[i,jp]) — exact integers (< 2^24) or ~1e9.
// Samples for mask m live on the opposite surface (m^1). Keys appended warp-aggregated.
__global__ void rowpass_kernel() {
    int m = blockIdx.x / HH;
    int i = blockIdx.x - m*HH;
    int cnt = (int)d_cnt[(m ^ 1)*HH + i];
    if (cnt == 0) return;
    __shared__ float4 gs4[WW/4];
    float* gs = (float*)gs4;
    for (int k = threadIdx.x; k < WW; k += blockDim.x) {
        unsigned short v = d_g16[m*HW + i*WW + k];
        gs[k] = (v == 65535) ? 1e9f : (float)v;
    }
    __syncthreads();
    const unsigned char* cols = d_cols + (m ^ 1)*HW + i*WW;
    int lane = threadIdx.x & 31;
    for (int t0 = 0; t0 < cnt; t0 += blockDim.x) {
        int t = t0 + threadIdx.x;
        bool act = (t < cnt);
        int key = 0;
        if (act) {
            float jj = (float)cols[t];
            float v = 3.0e9f;
            #pragma unroll
            for (int q = 0; q < WW/4; q++) {
                float4 g4 = gs4[q];
                float d0 = jj - (float)(4*q + 0);
                float d1 = jj - (float)(4*q + 1);
                float d2 = jj - (float)(4*q + 2);
                float d3 = jj - (float)(4*q + 3);
                v = fminf(v, fmaf(d0, d0, g4.x));
                v = fminf(v, fmaf(d1, d1, g4.y));
                v = fminf(v, fmaf(d2, d2, g4.z));
                v = fminf(v, fmaf(d3, d3, g4.w));
            }
            key = (v > 73000.0f) ? SENT_KEY : (int)v;   // v is an exact integer or ~1e9
        }
        unsigned msk = __ballot_sync(0xffffffffu, act);
        if (act) {
            int rank = __popc(msk & ((1u << lane) - 1u));
            int base = 0;
            if (rank == 0) base = atomicAdd(&d_kcnt[m], __popc(msk));
            base = __shfl_sync(msk, base, __ffs(msk) - 1);
            d_keys[m*HW + base + rank] = key;
        }
    }
}

// ---------------------------------------------------------------- per-mask selection over appended keys
// p100 = max key (rank n). p95 = rank ceil(0.95f*n) via smem coarse(288) + fine(256) histograms.
__global__ void select_kernel() {
    int m = blockIdx.x;
    int t = threadIdx.x;       // 256 threads
    int n = d_kcnt[m];
    if (n == 0) { if (t < 2) d_res[m*2 + t] = INFINITY; return; }
    __shared__ int hist[288];
    __shared__ int red[256];
    __shared__ int fine[256];
    __shared__ int cbS, rremS;
    for (int k = t; k < 288; k += 256) hist[k] = 0;
    fine[t] = 0;
    __syncthreads();
    const int* keys = d_keys + m*HW;
    int mx = 0;
    for (int k = t; k < n; k += 256) {
        int key = keys[k];
        mx = max(mx, key);
        atomicAdd(&hist[key >> 8], 1);
    }
    red[t] = mx;
    __syncthreads();
    #pragma unroll
    for (int s = 128; s > 0; s >>= 1) {
        if (t < s) red[t] = max(red[t], red[t + s]);
        __syncthreads();
    }
    if (t == 0) {
        int r95 = (int)ceilf(0.95f * (float)n);   // matches jnp f32 semantics
        if (r95 < 1) r95 = 1;
        if (r95 > n) r95 = n;
        int cum = 0, cb = 287;
        for (int k = 0; k < 288; k++) {
            if (cum + hist[k] >= r95) { cb = k; break; }
            cum += hist[k];
        }
        cbS = cb; rremS = r95 - cum;
    }
    __syncthreads();
    int cb = cbS;
    for (int k = t; k < n; k += 256) {
        int key = keys[k];
        if ((key >> 8) == cb) atomicAdd(&fine[key & 255], 1);
    }
    __syncthreads();
    if (t == 0) {
        int cum = 0, key95 = cb << 8;
        for (int k = 0; k < 256; k++) {
            cum += fine[k];
            if (cum >= rremS) { key95 += k; break; }
        }
        int keymax = red[0];
        d_res[m*2 + 0] = (key95  == SENT_KEY) ? sqrtf(1e9f) : sqrtf((float)key95);
        d_res[m*2 + 1] = (keymax == SENT_KEY) ? sqrtf(1e9f) : sqrtf((float)keymax);
    }
}

// ---------------------------------------------------------------- combine: max over directions, mean over 24 pairs
__global__ void final_kernel(float* __restrict__ out) {
    if (threadIdx.x == 0) {
        float s100 = 0.0f, s95 = 0.0f;
        #pragma unroll
        for (int p = 0; p < NP; p++) {
            s95  += fmaxf(d_res[(2*p)*2 + 0], d_res[(2*p+1)*2 + 0]);
            s100 += fmaxf(d_res[(2*p)*2 + 1], d_res[(2*p+1)*2 + 1]);
        }
        out[0] = s100 / (float)NP;
        out[1] = s95  / (float)NP;
    }
}

extern "C" void kernel_launch(void* const* d_in, const int* in_sizes, int n_in,
                              void* d_out, int out_size) {
    const float* logits = (const float*)d_in[0];
    const int*   target = (const int*)d_in[1];
    float* out = (float*)d_out;

    argmax_kernel     <<<(BB*HW/4 + 255)/256, 256>>>(logits);
    surfcompact_kernel<<<(NP*HH + 3)/4, 128>>>(target);
    colpass_kernel    <<<dim3(NM, 3), 64>>>();
    rowpass_kernel    <<<NM*HH, 128>>>();
    select_kernel     <<<NM, 256>>>();
    final_kernel      <<<1, 32>>>(out);
}

// round 7
// speedup vs baseline: 1.6602x; 1.6602x over previous
#include <cuda_runtime.h>
#include <math.h>

#define BB 8
#define CC 4
#define HH 192
#define WW 192
#define HW (HH*WW)
#define NP 24          // (batch, class) pairs: 8 * 3
#define NM 48          // masks: pair*2 + {0:pred surface, 1:gt surface}
#define SENT_KEY 73727 // sentinel key for f >= 1e9 (empty source surface)
#define RPB 16         // rows per rowpass block

__device__ unsigned char  d_pred[BB*HW];
__device__ unsigned char  d_surf[NM*HW];
__device__ unsigned char  d_cols[NM*HW];     // per-row compacted sample columns
__device__ short          d_cnt[NM*HH];      // samples per row
__device__ unsigned short d_g16[NM*HW];      // column-pass squared distance (65535 = inf)
__device__ int            d_keys[NM*HW];     // appended squared-distance keys per mask
__device__ int            d_kcnt[NM];        // append counters
__device__ float          d_res[NM*2];       // [m][0]=p95, [m][1]=p100

// ---------------------------------------------------------------- argmax (softmax monotone; first-max tie rule)
// Also clears the per-mask key counters (runs before rowpass).
__global__ void argmax_kernel(const float* __restrict__ logits) {
    int idx = blockIdx.x*blockDim.x + threadIdx.x;
    if (idx < NM) d_kcnt[idx] = 0;
    int pix4 = idx * 4;
    if (pix4 >= BB*HW) return;
    int b = pix4 / HW;
    int p = pix4 - b*HW;
    const float* base = logits + (size_t)b*CC*HW + p;
    float4 v0 = *(const float4*)(base);
    float4 v1 = *(const float4*)(base + HW);
    float4 v2 = *(const float4*)(base + 2*HW);
    float4 v3 = *(const float4*)(base + 3*HW);
    uchar4 r;
    #define AMAX(comp, dst) { \
        float bv = v0.comp; int bi = 0; \
        if (v1.comp > bv) { bv = v1.comp; bi = 1; } \
        if (v2.comp > bv) { bv = v2.comp; bi = 2; } \
        if (v3.comp > bv) { bv = v3.comp; bi = 3; } \
        dst = (unsigned char)bi; }
    AMAX(x, r.x) AMAX(y, r.y) AMAX(z, r.z) AMAX(w, r.w)
    #undef AMAX
    *(uchar4*)(d_pred + pix4) = r;
}

// ---------------------------------------------------------------- fused surface + row compaction
// One warp per (pair,row). Computes pred & gt 4-neighbor surfaces (border = background),
// writes d_surf (for colpass) and ballot-compacts surface columns into d_cols/d_cnt.
// target is int32 (JAX x64-disabled downcasts the reference's int64).
__global__ void surfcompact_kernel(const int* __restrict__ target) {
    int wid  = threadIdx.x >> 5;
    int lane = threadIdx.x & 31;
    int gw = blockIdx.x*4 + wid;                 // row id in [0, NP*HH)
    if (gw >= NP*HH) return;
    int pair = gw / HH;
    int i    = gw - pair*HH;
    int b = pair / 3;
    int c = pair - b*3 + 1;
    const unsigned char* P = d_pred + b*HW;
    const int* T = target + (size_t)b*HW;
    int mp = pair*2, mg = pair*2 + 1;
    unsigned char* outp = d_cols + mp*HW + i*WW;
    unsigned char* outg = d_cols + mg*HW + i*WW;
    int basep = 0, baseg = 0;
    #pragma unroll
    for (int ch = 0; ch < 6; ch++) {
        int j = ch*32 + lane;
        int pix = i*WW + j;
        // pred surface
        {
            bool fg = (P[pix] == c);
            bool s = false;
            if (fg) {
                bool up = (i > 0)    && (P[pix-WW] == c);
                bool dn = (i < HH-1) && (P[pix+WW] == c);
                bool lf = (j > 0)    && (P[pix-1]  == c);
                bool rt = (j < WW-1) && (P[pix+1]  == c);
                s = !(up && dn && lf && rt);
            }
            d_surf[mp*HW + pix] = s ? 1 : 0;
            unsigned msk = __ballot_sync(0xffffffffu, s);
            if (s) outp[basep + __popc(msk & ((1u << lane) - 1u))] = (unsigned char)j;
            basep += __popc(msk);
        }
        // gt surface
        {
            bool fg = (T[pix] == c);
            bool s = false;
            if (fg) {
                bool up = (i > 0)    && (T[pix-WW] == c);
                bool dn = (i < HH-1) && (T[pix+WW] == c);
                bool lf = (j > 0)    && (T[pix-1]  == c);
                bool rt = (j < WW-1) && (T[pix+1]  == c);
                s = !(up && dn && lf && rt);
            }
            d_surf[mg*HW + pix] = s ? 1 : 0;
            unsigned msk = __ballot_sync(0xffffffffu, s);
            if (s) outg[baseg + __popc(msk & ((1u << lane) - 1u))] = (unsigned char)j;
            baseg += __popc(msk);
        }
    }
    if (lane == 0) {
        d_cnt[mp*HH + i] = (short)basep;
        d_cnt[mg*HH + i] = (short)baseg;
    }
}

// ---------------------------------------------------------------- pass 1: per-column squared distance to nearest surface row
// grid (48 masks, 3 col-groups of 64). Forward: downward count into smem (0 <=> surface voxel).
// Backward: pure smem/register, write d^2 as u16 (65535 = empty column).
__global__ void colpass_kernel() {
    int m = blockIdx.x;
    int j = blockIdx.y*64 + threadIdx.x;
    int t = threadIdx.x;
    __shared__ unsigned char dtmp[HH*64];
    const unsigned char* s = d_surf + m*HW;
    unsigned short* g = d_g16 + m*HW;
    int cnt = 255;
    #pragma unroll 16
    for (int i = 0; i < HH; i++) {
        unsigned char sv = s[i*WW + j];
        cnt = sv ? 0 : min(cnt + 1, 255);
        dtmp[i*64 + t] = (unsigned char)cnt;
    }
    cnt = 255;
    #pragma unroll 16
    for (int i = HH-1; i >= 0; i--) {
        int du = (int)dtmp[i*64 + t];
        cnt = (du == 0) ? 0 : min(cnt + 1, 255);
        int d = min(cnt, du);
        g[i*WW + j] = (d >= HH) ? (unsigned short)65535 : (unsigned short)(d*d);
    }
}

// ---------------------------------------------------------------- pass 2: min-plus at sampled voxels via exact outward pruning
// f = min_jp (jj-jp)^2 + g[jp]. Scan d outward from jj; stop when d^2 >= v (g >= 0, so
// no farther jp can improve — exact). All values exact f32 integers (< 2^24) or ~1e9.
// 16 rows per block; samples flattened across the row-group. Keys appended warp-aggregated.
__global__ void __launch_bounds__(256) rowpass_kernel() {
    int m  = blockIdx.x;
    int i0 = blockIdx.y * RPB;
    __shared__ float gs[RPB][WW];
    __shared__ short offs[RPB + 1];
    const unsigned short* gsrc = d_g16 + m*HW + i0*WW;
    for (int k = threadIdx.x; k < RPB*WW; k += blockDim.x) {
        unsigned short v = gsrc[k];
        ((float*)gs)[k] = (v == 65535) ? 1e9f : (float)v;
    }
    if (threadIdx.x == 0) {
        int acc = 0;
        #pragma unroll
        for (int r = 0; r < RPB; r++) {
            offs[r] = (short)acc;
            acc += (int)d_cnt[(m ^ 1)*HH + i0 + r];
        }
        offs[RPB] = (short)acc;
    }
    __syncthreads();
    int total = (int)offs[RPB];
    int lane = threadIdx.x & 31;
    const unsigned char* colbase = d_cols + (m ^ 1)*HW + i0*WW;
    for (int t0 = 0; t0 < total; t0 += blockDim.x) {
        int t = t0 + threadIdx.x;
        bool act = (t < total);
        int key = 0;
        if (act) {
            int r = 0;
            #pragma unroll
            for (int rr = 1; rr < RPB; rr++) r += (t >= (int)offs[rr]);
            int idx = t - (int)offs[r];
            int jj = (int)colbase[r*WW + idx];
            const float* grow = gs[r];
            float v = grow[jj];
            for (int dd = 1; dd < WW; dd++) {
                float d2 = (float)(dd*dd);
                if (d2 >= v) break;
                int jl = jj - dd, jr = jj + dd;
                if (jl >= 0) v = fminf(v, d2 + grow[jl]);
                if (jr < WW) v = fminf(v, d2 + grow[jr]);
            }
            key = (v > 73000.0f) ? SENT_KEY : (int)v;
        }
        unsigned msk = __ballot_sync(0xffffffffu, act);
        if (act) {
            int rank = __popc(msk & ((1u << lane) - 1u));
            int base = 0;
            if (rank == 0) base = atomicAdd(&d_kcnt[m], __popc(msk));
            base = __shfl_sync(msk, base, __ffs(msk) - 1);
            d_keys[m*HW + base + rank] = key;
        }
    }
}

// ---------------------------------------------------------------- per-mask selection over appended keys
// p100 = max key (rank n). p95 = rank ceil(0.95f*n) via smem coarse(288) + fine(256) histograms.
__global__ void select_kernel() {
    int m = blockIdx.x;
    int t = threadIdx.x;       // 256 threads
    int n = d_kcnt[m];
    if (n == 0) { if (t < 2) d_res[m*2 + t] = INFINITY; return; }
    __shared__ int hist[288];
    __shared__ int red[256];
    __shared__ int fine[256];
    __shared__ int cbS, rremS;
    for (int k = t; k < 288; k += 256) hist[k] = 0;
    fine[t] = 0;
    __syncthreads();
    const int* keys = d_keys + m*HW;
    int mx = 0;
    for (int k = t; k < n; k += 256) {
        int key = keys[k];
        mx = max(mx, key);
        atomicAdd(&hist[key >> 8], 1);
    }
    red[t] = mx;
    __syncthreads();
    #pragma unroll
    for (int s = 128; s > 0; s >>= 1) {
        if (t < s) red[t] = max(red[t], red[t + s]);
        __syncthreads();
    }
    if (t == 0) {
        int r95 = (int)ceilf(0.95f * (float)n);   // matches jnp f32 semantics
        if (r95 < 1) r95 = 1;
        if (r95 > n) r95 = n;
        int cum = 0, cb = 287;
        for (int k = 0; k < 288; k++) {
            if (cum + hist[k] >= r95) { cb = k; break; }
            cum += hist[k];
        }
        cbS = cb; rremS = r95 - cum;
    }
    __syncthreads();
    int cb = cbS;
    for (int k = t; k < n; k += 256) {
        int key = keys[k];
        if ((key >> 8) == cb) atomicAdd(&fine[key & 255], 1);
    }
    __syncthreads();
    if (t == 0) {
        int cum = 0, key95 = cb << 8;
        for (int k = 0; k < 256; k++) {
            cum += fine[k];
            if (cum >= rremS) { key95 += k; break; }
        }
        int keymax = red[0];
        d_res[m*2 + 0] = (key95  == SENT_KEY) ? sqrtf(1e9f) : sqrtf((float)key95);
        d_res[m*2 + 1] = (keymax == SENT_KEY) ? sqrtf(1e9f) : sqrtf((float)keymax);
    }
}

// ---------------------------------------------------------------- combine: max over directions, mean over 24 pairs
__global__ void final_kernel(float* __restrict__ out) {
    if (threadIdx.x == 0) {
        float s100 = 0.0f, s95 = 0.0f;
        #pragma unroll
        for (int p = 0; p < NP; p++) {
            s95  += fmaxf(d_res[(2*p)*2 + 0], d_res[(2*p+1)*2 + 0]);
            s100 += fmaxf(d_res[(2*p)*2 + 1], d_res[(2*p+1)*2 + 1]);
        }
        out[0] = s100 / (float)NP;
        out[1] = s95  / (float)NP;
    }
}

extern "C" void kernel_launch(void* const* d_in, const int* in_sizes, int n_in,
                              void* d_out, int out_size) {
    const float* logits = (const float*)d_in[0];
    const int*   target = (const int*)d_in[1];
    float* out = (float*)d_out;

    argmax_kernel     <<<(BB*HW/4 + 255)/256, 256>>>(logits);
    surfcompact_kernel<<<(NP*HH + 3)/4, 128>>>(target);
    colpass_kernel    <<<dim3(NM, 3), 64>>>();
    rowpass_kernel    <<<dim3(NM, HH/RPB), 256>>>();
    select_kernel     <<<NM, 256>>>();
    final_kernel      <<<1, 32>>>(out);
}